// round 2
// baseline (speedup 1.0000x reference)
#include <cuda_runtime.h>

// out = 2048 * x @ (Wv @ Wo) + (2048 * bv @ Wo + bo)
// (softmax scores sum to exactly L=2048 per (b,h); einsum has no shared
//  contraction index, so attention collapses to a scalar multiply)

__device__ float g_Wc[1024 * 1024];   // Wv @ Wo
__device__ float g_c[1024];           // 2048 * bv @ Wo + bo

// ---------------------------------------------------------------------------
// c[j] = 2048 * sum_k bv[k]*Wo[k][j] + bo[j]
// ---------------------------------------------------------------------------
__global__ void bias_fold_kernel(const float* __restrict__ bv,
                                 const float* __restrict__ Wo,
                                 const float* __restrict__ bo,
                                 float* __restrict__ c)
{
    __shared__ float red[256];
    const int j = blockIdx.x;
    float s = 0.0f;
    #pragma unroll 4
    for (int k = threadIdx.x; k < 1024; k += 256)
        s += bv[k] * Wo[k * 1024 + j];
    red[threadIdx.x] = s;
    __syncthreads();
    #pragma unroll
    for (int off = 128; off > 0; off >>= 1) {
        if (threadIdx.x < off) red[threadIdx.x] += red[threadIdx.x + off];
        __syncthreads();
    }
    if (threadIdx.x == 0) c[j] = 2048.0f * red[0] + bo[j];
}

// ---------------------------------------------------------------------------
// C[M,N] = alpha * A[M,K] @ B[K,N] + bias[N]   (bias may be null)
// Register-blocked SIMT SGEMM, double-buffered shared memory.
// Requires M%BM==0, N%BN==0, K%BK==0 (true for all uses here).
// ---------------------------------------------------------------------------
template <int BM, int BN, int BK, int TM, int TN>
__global__ __launch_bounds__((BM / TM) * (BN / TN))
void sgemm_bias(const float* __restrict__ A, const float* __restrict__ B,
                float* __restrict__ C, int M, int N, int K,
                float alpha, const float* __restrict__ bias)
{
    constexpr int THREADS = (BM / TM) * (BN / TN);   // 256 in both configs
    constexpr int KV = BK / 4;                        // float4 per A-tile row
    constexpr int NV = BN / 4;                        // float4 per B-tile row
    constexpr int A_LD = (BM * BK / 4) / THREADS;
    constexpr int B_LD = (BK * BN / 4) / THREADS;

    __shared__ __align__(16) float As[2][BK][BM];
    __shared__ __align__(16) float Bs[2][BK][BN];

    const int tid  = threadIdx.x;
    const int tx   = tid % (BN / TN);
    const int ty   = tid / (BN / TN);
    const int row0 = blockIdx.y * BM;
    const int col0 = blockIdx.x * BN;

    const float* Ab = A + (size_t)row0 * K;
    const float* Bb = B + col0;

    float4 aReg[A_LD], bReg[B_LD];
    float  acc[TM][TN];
    #pragma unroll
    for (int i = 0; i < TM; i++)
        #pragma unroll
        for (int j = 0; j < TN; j++) acc[i][j] = 0.0f;

    // ---- load first K-tile into registers ----
    #pragma unroll
    for (int i = 0; i < A_LD; i++) {
        const int idx = tid + i * THREADS;
        const int r = idx / KV, c4 = idx % KV;
        aReg[i] = *reinterpret_cast<const float4*>(&Ab[(size_t)r * K + c4 * 4]);
    }
    #pragma unroll
    for (int i = 0; i < B_LD; i++) {
        const int idx = tid + i * THREADS;
        const int r = idx / NV, c4 = idx % NV;
        bReg[i] = *reinterpret_cast<const float4*>(&Bb[(size_t)r * N + c4 * 4]);
    }
    // ---- stage into buffer 0 (A transposed to [BK][BM]) ----
    #pragma unroll
    for (int i = 0; i < A_LD; i++) {
        const int idx = tid + i * THREADS;
        const int r = idx / KV, c4 = idx % KV;
        As[0][c4 * 4 + 0][r] = aReg[i].x;
        As[0][c4 * 4 + 1][r] = aReg[i].y;
        As[0][c4 * 4 + 2][r] = aReg[i].z;
        As[0][c4 * 4 + 3][r] = aReg[i].w;
    }
    #pragma unroll
    for (int i = 0; i < B_LD; i++) {
        const int idx = tid + i * THREADS;
        const int r = idx / NV, c4 = idx % NV;
        *reinterpret_cast<float4*>(&Bs[0][r][c4 * 4]) = bReg[i];
    }
    __syncthreads();

    const int NT = K / BK;
    for (int kt = 0; kt < NT; kt++) {
        const int buf = kt & 1;

        // prefetch next tile from global into registers
        if (kt + 1 < NT) {
            const int k0 = (kt + 1) * BK;
            #pragma unroll
            for (int i = 0; i < A_LD; i++) {
                const int idx = tid + i * THREADS;
                const int r = idx / KV, c4 = idx % KV;
                aReg[i] = *reinterpret_cast<const float4*>(&Ab[(size_t)r * K + k0 + c4 * 4]);
            }
            #pragma unroll
            for (int i = 0; i < B_LD; i++) {
                const int idx = tid + i * THREADS;
                const int r = idx / NV, c4 = idx % NV;
                bReg[i] = *reinterpret_cast<const float4*>(&Bb[(size_t)(k0 + r) * N + c4 * 4]);
            }
        }

        // compute on current buffer
        #pragma unroll
        for (int k = 0; k < BK; k++) {
            float a[TM], b[TN];
            #pragma unroll
            for (int i = 0; i < TM; i += 4)
                *reinterpret_cast<float4*>(&a[i]) =
                    *reinterpret_cast<const float4*>(&As[buf][k][ty * TM + i]);
            #pragma unroll
            for (int j = 0; j < TN; j += 4)
                *reinterpret_cast<float4*>(&b[j]) =
                    *reinterpret_cast<const float4*>(&Bs[buf][k][tx * TN + j]);
            #pragma unroll
            for (int i = 0; i < TM; i++)
                #pragma unroll
                for (int j = 0; j < TN; j++)
                    acc[i][j] += a[i] * b[j];
        }

        // stage prefetched tile into the other buffer
        if (kt + 1 < NT) {
            const int nb = buf ^ 1;
            #pragma unroll
            for (int i = 0; i < A_LD; i++) {
                const int idx = tid + i * THREADS;
                const int r = idx / KV, c4 = idx % KV;
                As[nb][c4 * 4 + 0][r] = aReg[i].x;
                As[nb][c4 * 4 + 1][r] = aReg[i].y;
                As[nb][c4 * 4 + 2][r] = aReg[i].z;
                As[nb][c4 * 4 + 3][r] = aReg[i].w;
            }
            #pragma unroll
            for (int i = 0; i < B_LD; i++) {
                const int idx = tid + i * THREADS;
                const int r = idx / NV, c4 = idx % NV;
                *reinterpret_cast<float4*>(&Bs[nb][r][c4 * 4]) = bReg[i];
            }
            __syncthreads();
        }
    }

    // ---- epilogue: C = alpha*acc + bias ----
    float bb[TN];
    #pragma unroll
    for (int j = 0; j < TN; j++)
        bb[j] = (bias != nullptr) ? bias[col0 + tx * TN + j] : 0.0f;

    #pragma unroll
    for (int i = 0; i < TM; i++) {
        float* Cp = &C[(size_t)(row0 + ty * TM + i) * N + (col0 + tx * TN)];
        #pragma unroll
        for (int j = 0; j < TN; j += 4) {
            float4 v;
            v.x = alpha * acc[i][j + 0] + bb[j + 0];
            v.y = alpha * acc[i][j + 1] + bb[j + 1];
            v.z = alpha * acc[i][j + 2] + bb[j + 2];
            v.w = alpha * acc[i][j + 3] + bb[j + 3];
            *reinterpret_cast<float4*>(&Cp[j]) = v;
        }
    }
}

// ---------------------------------------------------------------------------
extern "C" void kernel_launch(void* const* d_in, const int* in_sizes, int n_in,
                              void* d_out, int out_size)
{
    // metadata order: x, encoder_x, Wq, bq, Wk, bk, Wv, bv, Wo, bo
    const float* x  = (const float*)d_in[0];
    const float* Wv = (const float*)d_in[6];
    const float* bv = (const float*)d_in[7];
    const float* Wo = (const float*)d_in[8];
    const float* bo = (const float*)d_in[9];
    float* out = (float*)d_out;

    float* Wc = nullptr;
    float* c  = nullptr;
    cudaGetSymbolAddress((void**)&Wc, g_Wc);
    cudaGetSymbolAddress((void**)&c,  g_c);

    // 1) Wc = Wv @ Wo  (1024x1024x1024) — 64x64 tiles -> 256 CTAs for parallelism
    {
        dim3 grid(1024 / 64, 1024 / 64);
        sgemm_bias<64, 64, 16, 4, 4><<<grid, 256>>>(Wv, Wo, Wc,
                                                    1024, 1024, 1024,
                                                    1.0f, nullptr);
    }
    // 2) c = 2048 * bv @ Wo + bo
    bias_fold_kernel<<<1024, 256>>>(bv, Wo, bo, c);

    // 3) out = 2048 * x @ Wc + c  (8192x1024x1024)
    {
        dim3 grid(1024 / 128, 8192 / 128);
        sgemm_bias<128, 128, 16, 8, 8><<<grid, 256>>>(x, Wc, out,
                                                      8192, 1024, 1024,
                                                      2048.0f, c);
    }
    (void)in_sizes; (void)n_in; (void)out_size;
}

// round 4
// speedup vs baseline: 1.6760x; 1.6760x over previous
#include <cuda_runtime.h>
#include <cuda_bf16.h>
#include <cstdint>

// ===========================================================================
// out = 2048 * x @ (Wv @ Wo) + (2048 * bv @ Wo + bo)
// (softmax rows sum to 1; einsum 'bvhd,bhqk->bvhd' has no shared contraction
//  index, so attention collapses to scalar 2048)
//
// tcgen05 is unavailable through this bench (ptxas targets sm_103, not
// sm_103a), so GEMMs use warp-level mma.sync.m16n8k16 bf16 (HMMA path).
// fp32 operands are split in-kernel into bf16 hi/lo; 3-term MMA
// (AhBh + AhBl + AlBh) gives ~1e-5 relative accuracy.
// ===========================================================================

__device__ float g_WcT[1024 * 1024];   // (Wv @ Wo)^T, fp32  (rows=o, K=i)
__device__ float g_Wot[1024 * 1024];   // Wo^T, fp32
__device__ float g_c[1024];            // 2048 * bv @ Wo + bo

__device__ __forceinline__ uint32_t smem_u32(const void* p) {
    uint32_t a;
    asm("{ .reg .u64 t; cvta.to.shared.u64 t, %1; cvt.u32.u64 %0, t; }"
        : "=r"(a) : "l"(p));
    return a;
}

__device__ __forceinline__ void ldsm4(uint32_t* r, uint32_t addr) {
    asm volatile("ldmatrix.sync.aligned.m8n8.x4.shared.b16 {%0,%1,%2,%3}, [%4];"
                 : "=r"(r[0]), "=r"(r[1]), "=r"(r[2]), "=r"(r[3]) : "r"(addr));
}

__device__ __forceinline__ void mma16816(float* c, const uint32_t* a, const uint32_t* b) {
    asm volatile(
        "mma.sync.aligned.m16n8k16.row.col.f32.bf16.bf16.f32 "
        "{%0,%1,%2,%3}, {%4,%5,%6,%7}, {%8,%9}, {%0,%1,%2,%3};"
        : "+f"(c[0]), "+f"(c[1]), "+f"(c[2]), "+f"(c[3])
        : "r"(a[0]), "r"(a[1]), "r"(a[2]), "r"(a[3]), "r"(b[0]), "r"(b[1]));
}

// ---------------------------------------------------------------------------
// Shared-memory tile geometry: bf16 [128 rows][32 k] with padded stride 40
// elems (80 B) -> ldmatrix 8-row reads cover all 32 banks exactly once.
// ---------------------------------------------------------------------------
constexpr int LDS_ELEM = 40;                 // padded row stride in bf16
constexpr int LDS_B    = LDS_ELEM * 2;       // 80 bytes
constexpr uint32_t MAT_BYTES = 128u * LDS_B; // 10240 B per matrix
constexpr uint32_t OFF_ALO = MAT_BYTES;
constexpr uint32_t OFF_BHI = 2 * MAT_BYTES;
constexpr uint32_t OFF_BLO = 3 * MAT_BYTES;
constexpr uint32_t STAGE   = 4 * MAT_BYTES;  // 40960 B per buffer
constexpr uint32_t SMEM_BYTES = 2 * STAGE;   // 81920 B

// split float4 -> bf16 hi/lo, store 8 B each into (r, c4*4) of hi/lo matrices
__device__ __forceinline__ void sts_split(uint32_t hBase, uint32_t lBase,
                                          int r, int c4, float4 v) {
    __nv_bfloat16 h0 = __float2bfloat16_rn(v.x);
    __nv_bfloat16 h1 = __float2bfloat16_rn(v.y);
    __nv_bfloat16 h2 = __float2bfloat16_rn(v.z);
    __nv_bfloat16 h3 = __float2bfloat16_rn(v.w);
    __nv_bfloat16 l0 = __float2bfloat16_rn(v.x - __bfloat162float(h0));
    __nv_bfloat16 l1 = __float2bfloat16_rn(v.y - __bfloat162float(h1));
    __nv_bfloat16 l2 = __float2bfloat16_rn(v.z - __bfloat162float(h2));
    __nv_bfloat16 l3 = __float2bfloat16_rn(v.w - __bfloat162float(h3));
    const uint32_t off = (uint32_t)(r * LDS_B + c4 * 8);
    __nv_bfloat162 hp0 = __halves2bfloat162(h0, h1);
    __nv_bfloat162 hp1 = __halves2bfloat162(h2, h3);
    __nv_bfloat162 lp0 = __halves2bfloat162(l0, l1);
    __nv_bfloat162 lp1 = __halves2bfloat162(l2, l3);
    asm volatile("st.shared.v2.b32 [%0], {%1, %2};"
                 :: "r"(hBase + off),
                    "r"(*reinterpret_cast<uint32_t*>(&hp0)),
                    "r"(*reinterpret_cast<uint32_t*>(&hp1)));
    asm volatile("st.shared.v2.b32 [%0], {%1, %2};"
                 :: "r"(lBase + off),
                    "r"(*reinterpret_cast<uint32_t*>(&lp0)),
                    "r"(*reinterpret_cast<uint32_t*>(&lp1)));
}

// ---------------------------------------------------------------------------
// C[M,N] = alpha * A[M,K] @ B[N,K]^T + bias[N]
// A: [M,K] row-major fp32, B: [N,K] row-major fp32. 128x128 CTA tile, BK=32.
// 8 warps: warp_m = wid>>2 (2), warp_n = wid&3 (4); warp tile 64x32.
// ---------------------------------------------------------------------------
__global__ void __launch_bounds__(256, 1)
mma_gemm(const float* __restrict__ A, const float* __restrict__ B,
         float* __restrict__ C, int M, int N, int K,
         float alpha, const float* __restrict__ bias)
{
    extern __shared__ __align__(128) char smem_raw[];
    const uint32_t sb = smem_u32(smem_raw);

    const int tid = threadIdx.x;
    const int wid = tid >> 5;
    const int lane = tid & 31;
    const int warp_m = wid >> 2;           // 0..1
    const int warp_n = wid & 3;            // 0..3
    const int row0 = blockIdx.y * 128;
    const int col0 = blockIdx.x * 128;

    // per-lane ldmatrix address offsets (within a matrix, bytes)
    // A x4 tiles: sub=lane>>3 -> (row += (sub&1)*8, col += (sub>>1)*8)
    const uint32_t aOff = (uint32_t)((warp_m * 64 + (lane & 7) + ((lane >> 3) & 1) * 8) * LDS_B
                                     + (lane >> 4) * 16);
    // B x4 tiles: sub -> (row += (sub>>1)*8, col += (sub&1)*8)
    const uint32_t bOff = (uint32_t)((warp_n * 32 + (lane & 7) + ((lane >> 4) & 1) * 8) * LDS_B
                                     + ((lane >> 3) & 1) * 16);

    float acc[4][4][4];
    #pragma unroll
    for (int mt = 0; mt < 4; mt++)
        #pragma unroll
        for (int nt = 0; nt < 4; nt++)
            #pragma unroll
            for (int e = 0; e < 4; e++) acc[mt][nt][e] = 0.0f;

    const int NT = K >> 5;                 // K chunks of 32
    const int ldr = tid >> 3;              // load row (0..127 over 4 iters)
    const int ldc = tid & 7;               // float4 column within 32-elem chunk

    float4 pa[4], pb[4];

    auto ldg = [&](int kt) {
        const int k0 = kt << 5;
        #pragma unroll
        for (int i = 0; i < 4; i++) {
            const int r = ldr + i * 32;
            pa[i] = *reinterpret_cast<const float4*>(A + (size_t)(row0 + r) * K + k0 + ldc * 4);
            pb[i] = *reinterpret_cast<const float4*>(B + (size_t)(col0 + r) * K + k0 + ldc * 4);
        }
    };
    auto sts = [&](int s) {
        const uint32_t base = sb + (uint32_t)s * STAGE;
        #pragma unroll
        for (int i = 0; i < 4; i++) {
            const int r = ldr + i * 32;
            sts_split(base,            base + OFF_ALO, r, ldc, pa[i]);
            sts_split(base + OFF_BHI,  base + OFF_BLO, r, ldc, pb[i]);
        }
    };
    auto compute = [&](int s) {
        const uint32_t base = sb + (uint32_t)s * STAGE;
        #pragma unroll
        for (int ks = 0; ks < 2; ks++) {
            uint32_t ah[4][4], al[4][4], bh[2][4], bl[2][4];
            #pragma unroll
            for (int mt = 0; mt < 4; mt++) {
                const uint32_t ad = base + aOff + (uint32_t)(mt * 16 * LDS_B + ks * 32);
                ldsm4(ah[mt], ad);
                ldsm4(al[mt], ad + OFF_ALO);
            }
            #pragma unroll
            for (int np = 0; np < 2; np++) {
                const uint32_t bd = base + OFF_BHI + bOff + (uint32_t)(np * 16 * LDS_B + ks * 32);
                ldsm4(bh[np], bd);
                ldsm4(bl[np], bd + MAT_BYTES);   // BLO = BHI + MAT_BYTES
            }
            #pragma unroll
            for (int mt = 0; mt < 4; mt++)
                #pragma unroll
                for (int nt = 0; nt < 4; nt++) {
                    const uint32_t* bhp = &bh[nt >> 1][(nt & 1) * 2];
                    const uint32_t* blp = &bl[nt >> 1][(nt & 1) * 2];
                    mma16816(acc[mt][nt], ah[mt], bhp);
                    mma16816(acc[mt][nt], ah[mt], blp);
                    mma16816(acc[mt][nt], al[mt], bhp);
                }
        }
    };

    ldg(0);
    sts(0);
    __syncthreads();

    for (int kt = 0; kt < NT; kt++) {
        const int s = kt & 1;
        if (kt + 1 < NT) ldg(kt + 1);
        compute(s);
        if (kt + 1 < NT) {
            sts(s ^ 1);
            __syncthreads();
        }
    }

    // ---- epilogue: alpha*acc + bias, float2 stores ----
    const int erow = row0 + warp_m * 64 + (lane >> 2);
    const int ecol = col0 + warp_n * 32 + (lane & 3) * 2;
    #pragma unroll
    for (int mt = 0; mt < 4; mt++) {
        #pragma unroll
        for (int nt = 0; nt < 4; nt++) {
            const int cg = ecol + nt * 8;
            float b0 = bias ? bias[cg]     : 0.0f;
            float b1 = bias ? bias[cg + 1] : 0.0f;
            float2 v0, v1;
            v0.x = fmaf(alpha, acc[mt][nt][0], b0);
            v0.y = fmaf(alpha, acc[mt][nt][1], b1);
            v1.x = fmaf(alpha, acc[mt][nt][2], b0);
            v1.y = fmaf(alpha, acc[mt][nt][3], b1);
            *reinterpret_cast<float2*>(C + (size_t)(erow + mt * 16) * N + cg)     = v0;
            *reinterpret_cast<float2*>(C + (size_t)(erow + mt * 16 + 8) * N + cg) = v1;
        }
    }
}

// ---------------------------------------------------------------------------
// Wot[o,m] = Wo[m,o]   (1024x1024 fp32 transpose)
// ---------------------------------------------------------------------------
__global__ void transpose_1024(const float* __restrict__ in, float* __restrict__ out) {
    __shared__ float t[32][33];
    const int bx = blockIdx.x * 32, by = blockIdx.y * 32;
    const int tx = threadIdx.x, ty = threadIdx.y;   // block 32x8
    #pragma unroll
    for (int i = 0; i < 32; i += 8)
        t[ty + i][tx] = in[(size_t)(by + ty + i) * 1024 + bx + tx];
    __syncthreads();
    #pragma unroll
    for (int i = 0; i < 32; i += 8)
        out[(size_t)(bx + ty + i) * 1024 + by + tx] = t[tx][ty + i];
}

// ---------------------------------------------------------------------------
// c[j] = 2048 * sum_k bv[k]*Wo[k][j] + bo[j]
// ---------------------------------------------------------------------------
__global__ void bias_fold_kernel(const float* __restrict__ bv,
                                 const float* __restrict__ Wo,
                                 const float* __restrict__ bo,
                                 float* __restrict__ c)
{
    __shared__ float red[256];
    const int j = blockIdx.x;
    float s = 0.0f;
    #pragma unroll 4
    for (int k = threadIdx.x; k < 1024; k += 256)
        s += bv[k] * Wo[k * 1024 + j];
    red[threadIdx.x] = s;
    __syncthreads();
    #pragma unroll
    for (int off = 128; off > 0; off >>= 1) {
        if (threadIdx.x < off) red[threadIdx.x] += red[threadIdx.x + off];
        __syncthreads();
    }
    if (threadIdx.x == 0) c[j] = 2048.0f * red[0] + bo[j];
}

// ---------------------------------------------------------------------------
extern "C" void kernel_launch(void* const* d_in, const int* in_sizes, int n_in,
                              void* d_out, int out_size)
{
    // metadata order: x, encoder_x, Wq, bq, Wk, bk, Wv, bv, Wo, bo
    const float* x  = (const float*)d_in[0];
    const float* Wv = (const float*)d_in[6];
    const float* bv = (const float*)d_in[7];
    const float* Wo = (const float*)d_in[8];
    const float* bo = (const float*)d_in[9];
    float* out = (float*)d_out;

    float *WcT = nullptr, *Wot = nullptr, *c = nullptr;
    cudaGetSymbolAddress((void**)&WcT, g_WcT);
    cudaGetSymbolAddress((void**)&Wot, g_Wot);
    cudaGetSymbolAddress((void**)&c,   g_c);

    cudaFuncSetAttribute(mma_gemm, cudaFuncAttributeMaxDynamicSharedMemorySize,
                         (int)SMEM_BYTES);

    // 0) Wot = Wo^T
    transpose_1024<<<dim3(32, 32), dim3(32, 8)>>>(Wo, Wot);
    // 1) c = 2048 * bv @ Wo + bo
    bias_fold_kernel<<<1024, 256>>>(bv, Wo, bo, c);
    // 2) WcT[o,i] = sum_m Wot[o,m] * Wv[i,m]   (A=Wot, B=Wv, both K-major)
    mma_gemm<<<dim3(8, 8), 256, SMEM_BYTES>>>(Wot, Wv, WcT,
                                              1024, 1024, 1024, 1.0f, nullptr);
    // 3) out[r,o] = 2048 * sum_i x[r,i] * WcT[o,i] + c[o]
    mma_gemm<<<dim3(8, 64), 256, SMEM_BYTES>>>(x, WcT, out,
                                               8192, 1024, 1024, 2048.0f, c);

    (void)in_sizes; (void)n_in; (void)out_size;
}

// round 5
// speedup vs baseline: 2.6966x; 1.6090x over previous
#include <cuda_runtime.h>
#include <cuda_bf16.h>
#include <cstdint>

// ===========================================================================
// out = 2048 * x @ (Wv @ Wo) + (2048 * bv @ Wo + bo)
// (softmax rows sum to 1; einsum 'bvhd,bhqk->bvhd' has no shared contraction
//  index, so attention collapses to scalar 2048)
//
// tcgen05 unavailable (bench ptxas targets sm_103, not sm_103a) -> warp-level
// mma.sync.m16n8k16 bf16. fp32 operands split in-kernel into bf16 hi/lo;
// 3-term MMA (AhBh + AhBl + AlBh), issued TERM-MAJOR so dependent MMAs on the
// same accumulator are 16 instructions apart (R4 was 1 apart -> issue=25%).
// ===========================================================================

__device__ float g_WcT[1024 * 1024];   // (Wv @ Wo)^T, fp32  (rows=o, K=i)
__device__ float g_Wot[1024 * 1024];   // Wo^T, fp32
__device__ float g_c[1024];            // 2048 * bv @ Wo + bo

__device__ __forceinline__ uint32_t smem_u32(const void* p) {
    uint32_t a;
    asm("{ .reg .u64 t; cvta.to.shared.u64 t, %1; cvt.u32.u64 %0, t; }"
        : "=r"(a) : "l"(p));
    return a;
}

__device__ __forceinline__ void ldsm4(uint32_t* r, uint32_t addr) {
    asm volatile("ldmatrix.sync.aligned.m8n8.x4.shared.b16 {%0,%1,%2,%3}, [%4];"
                 : "=r"(r[0]), "=r"(r[1]), "=r"(r[2]), "=r"(r[3]) : "r"(addr));
}

__device__ __forceinline__ void mma16816(float* c, const uint32_t* a, const uint32_t* b) {
    asm volatile(
        "mma.sync.aligned.m16n8k16.row.col.f32.bf16.bf16.f32 "
        "{%0,%1,%2,%3}, {%4,%5,%6,%7}, {%8,%9}, {%0,%1,%2,%3};"
        : "+f"(c[0]), "+f"(c[1]), "+f"(c[2]), "+f"(c[3])
        : "r"(a[0]), "r"(a[1]), "r"(a[2]), "r"(a[3]), "r"(b[0]), "r"(b[1]));
}

// bf16 [rows][32] tiles, padded row stride 40 bf16 (80 B): ldmatrix 8-row
// reads cover all 32 banks exactly once.
constexpr int LDS_B = 80;

// split float4 -> bf16 hi/lo, 8 B stores into (r, c4*4) of hi/lo matrices
__device__ __forceinline__ void sts_split(uint32_t hBase, uint32_t lBase,
                                          int r, int c4, float4 v) {
    __nv_bfloat16 h0 = __float2bfloat16_rn(v.x);
    __nv_bfloat16 h1 = __float2bfloat16_rn(v.y);
    __nv_bfloat16 h2 = __float2bfloat16_rn(v.z);
    __nv_bfloat16 h3 = __float2bfloat16_rn(v.w);
    __nv_bfloat16 l0 = __float2bfloat16_rn(v.x - __bfloat162float(h0));
    __nv_bfloat16 l1 = __float2bfloat16_rn(v.y - __bfloat162float(h1));
    __nv_bfloat16 l2 = __float2bfloat16_rn(v.z - __bfloat162float(h2));
    __nv_bfloat16 l3 = __float2bfloat16_rn(v.w - __bfloat162float(h3));
    const uint32_t off = (uint32_t)(r * LDS_B + c4 * 8);
    __nv_bfloat162 hp0 = __halves2bfloat162(h0, h1);
    __nv_bfloat162 hp1 = __halves2bfloat162(h2, h3);
    __nv_bfloat162 lp0 = __halves2bfloat162(l0, l1);
    __nv_bfloat162 lp1 = __halves2bfloat162(l2, l3);
    asm volatile("st.shared.v2.b32 [%0], {%1, %2};"
                 :: "r"(hBase + off),
                    "r"(*reinterpret_cast<uint32_t*>(&hp0)),
                    "r"(*reinterpret_cast<uint32_t*>(&hp1)));
    asm volatile("st.shared.v2.b32 [%0], {%1, %2};"
                 :: "r"(lBase + off),
                    "r"(*reinterpret_cast<uint32_t*>(&lp0)),
                    "r"(*reinterpret_cast<uint32_t*>(&lp1)));
}

// ---------------------------------------------------------------------------
// C[M,N] = alpha * A[M,K] @ B[N,K]^T + bias[N]
// A: [M,K] row-major fp32, B: [N,K] row-major fp32. CTA tile BM x BN, BK=32.
// Warp tile WM x WN; 256 threads (8 warps) required by the configs used.
// ---------------------------------------------------------------------------
template <int BM, int BN, int WM, int WN>
__global__ void __launch_bounds__(256, 1)
mma_gemm(const float* __restrict__ A, const float* __restrict__ B,
         float* __restrict__ C, int M, int N, int K,
         float alpha, const float* __restrict__ bias)
{
    constexpr int WARPS_N = BN / WN;
    constexpr int MT  = WM / 16;             // 16-row mma tiles per warp
    constexpr int NTT = WN / 8;              // 8-col mma tiles per warp
    constexpr int NP  = WN / 16;             // 16-col ldsm groups per warp
    constexpr int A_IT = BM * 8 / 256;       // float4 loads per thread (A)
    constexpr int B_IT = BN * 8 / 256;       // float4 loads per thread (B)
    constexpr uint32_t OFF_ALO = (uint32_t)BM * LDS_B;
    constexpr uint32_t OFF_BHI = 2u * BM * LDS_B;
    constexpr uint32_t OFF_BLO = OFF_BHI + (uint32_t)BN * LDS_B;
    constexpr uint32_t STAGE   = 2u * (BM + BN) * LDS_B;

    extern __shared__ __align__(128) char smem_raw[];
    const uint32_t sb = smem_u32(smem_raw);

    const int tid = threadIdx.x;
    const int wid = tid >> 5;
    const int lane = tid & 31;
    const int warp_m = wid / WARPS_N;
    const int warp_n = wid % WARPS_N;
    const int row0 = blockIdx.y * BM;
    const int col0 = blockIdx.x * BN;

    // ldmatrix lane->addr offsets (bytes, within a matrix)
    const uint32_t aOff = (uint32_t)((warp_m * WM + (lane & 7) + ((lane >> 3) & 1) * 8) * LDS_B
                                     + (lane >> 4) * 16);
    const uint32_t bOff = (uint32_t)((warp_n * WN + (lane & 7) + ((lane >> 4) & 1) * 8) * LDS_B
                                     + ((lane >> 3) & 1) * 16);

    float acc[MT][NTT][4];
    #pragma unroll
    for (int mt = 0; mt < MT; mt++)
        #pragma unroll
        for (int nt = 0; nt < NTT; nt++)
            #pragma unroll
            for (int e = 0; e < 4; e++) acc[mt][nt][e] = 0.0f;

    const int NT = K >> 5;
    const int ldr = tid >> 3;
    const int ldc = tid & 7;

    float4 pa[A_IT], pb[B_IT];

    auto ldg = [&](int kt) {
        const int k0 = kt << 5;
        #pragma unroll
        for (int i = 0; i < A_IT; i++)
            pa[i] = *reinterpret_cast<const float4*>(
                A + (size_t)(row0 + ldr + i * 32) * K + k0 + ldc * 4);
        #pragma unroll
        for (int i = 0; i < B_IT; i++)
            pb[i] = *reinterpret_cast<const float4*>(
                B + (size_t)(col0 + ldr + i * 32) * K + k0 + ldc * 4);
    };
    auto sts = [&](int s) {
        const uint32_t base = sb + (uint32_t)s * STAGE;
        #pragma unroll
        for (int i = 0; i < A_IT; i++)
            sts_split(base, base + OFF_ALO, ldr + i * 32, ldc, pa[i]);
        #pragma unroll
        for (int i = 0; i < B_IT; i++)
            sts_split(base + OFF_BHI, base + OFF_BLO, ldr + i * 32, ldc, pb[i]);
    };
    auto compute = [&](int s) {
        const uint32_t base = sb + (uint32_t)s * STAGE;
        #pragma unroll
        for (int ks = 0; ks < 2; ks++) {
            uint32_t ah[MT][4], al[MT][4], bh[NP][4], bl[NP][4];
            #pragma unroll
            for (int mt = 0; mt < MT; mt++) {
                const uint32_t ad = base + aOff + (uint32_t)(mt * 16 * LDS_B + ks * 32);
                ldsm4(ah[mt], ad);
                ldsm4(al[mt], ad + OFF_ALO);
            }
            #pragma unroll
            for (int np = 0; np < NP; np++) {
                const uint32_t bd = base + OFF_BHI + bOff + (uint32_t)(np * 16 * LDS_B + ks * 32);
                ldsm4(bh[np], bd);
                ldsm4(bl[np], bd + (uint32_t)BN * LDS_B);
            }
            // term-major: dependent MMAs on one acc are MT*NTT apart
            #pragma unroll
            for (int mt = 0; mt < MT; mt++)
                #pragma unroll
                for (int nt = 0; nt < NTT; nt++)
                    mma16816(acc[mt][nt], ah[mt], &bh[nt >> 1][(nt & 1) * 2]);
            #pragma unroll
            for (int mt = 0; mt < MT; mt++)
                #pragma unroll
                for (int nt = 0; nt < NTT; nt++)
                    mma16816(acc[mt][nt], ah[mt], &bl[nt >> 1][(nt & 1) * 2]);
            #pragma unroll
            for (int mt = 0; mt < MT; mt++)
                #pragma unroll
                for (int nt = 0; nt < NTT; nt++)
                    mma16816(acc[mt][nt], al[mt], &bh[nt >> 1][(nt & 1) * 2]);
        }
    };

    ldg(0);
    sts(0);
    __syncthreads();

    for (int kt = 0; kt < NT; kt++) {
        const int s = kt & 1;
        if (kt + 1 < NT) ldg(kt + 1);
        compute(s);
        if (kt + 1 < NT) {
            sts(s ^ 1);
            __syncthreads();
        }
    }

    // ---- epilogue ----
    const int erow = row0 + warp_m * WM + (lane >> 2);
    const int ecol = col0 + warp_n * WN + (lane & 3) * 2;
    #pragma unroll
    for (int mt = 0; mt < MT; mt++) {
        #pragma unroll
        for (int nt = 0; nt < NTT; nt++) {
            const int cg = ecol + nt * 8;
            const float b0 = bias ? bias[cg]     : 0.0f;
            const float b1 = bias ? bias[cg + 1] : 0.0f;
            float2 v0, v1;
            v0.x = fmaf(alpha, acc[mt][nt][0], b0);
            v0.y = fmaf(alpha, acc[mt][nt][1], b1);
            v1.x = fmaf(alpha, acc[mt][nt][2], b0);
            v1.y = fmaf(alpha, acc[mt][nt][3], b1);
            *reinterpret_cast<float2*>(C + (size_t)(erow + mt * 16) * N + cg)     = v0;
            *reinterpret_cast<float2*>(C + (size_t)(erow + mt * 16 + 8) * N + cg) = v1;
        }
    }
}

// ---------------------------------------------------------------------------
__global__ void transpose_1024(const float* __restrict__ in, float* __restrict__ out) {
    __shared__ float t[32][33];
    const int bx = blockIdx.x * 32, by = blockIdx.y * 32;
    const int tx = threadIdx.x, ty = threadIdx.y;   // block 32x8
    #pragma unroll
    for (int i = 0; i < 32; i += 8)
        t[ty + i][tx] = in[(size_t)(by + ty + i) * 1024 + bx + tx];
    __syncthreads();
    #pragma unroll
    for (int i = 0; i < 32; i += 8)
        out[(size_t)(bx + ty + i) * 1024 + by + tx] = t[tx][ty + i];
}

__global__ void bias_fold_kernel(const float* __restrict__ bv,
                                 const float* __restrict__ Wo,
                                 const float* __restrict__ bo,
                                 float* __restrict__ c)
{
    __shared__ float red[256];
    const int j = blockIdx.x;
    float s = 0.0f;
    #pragma unroll 4
    for (int k = threadIdx.x; k < 1024; k += 256)
        s += bv[k] * Wo[k * 1024 + j];
    red[threadIdx.x] = s;
    __syncthreads();
    #pragma unroll
    for (int off = 128; off > 0; off >>= 1) {
        if (threadIdx.x < off) red[threadIdx.x] += red[threadIdx.x + off];
        __syncthreads();
    }
    if (threadIdx.x == 0) c[j] = 2048.0f * red[0] + bo[j];
}

// ---------------------------------------------------------------------------
extern "C" void kernel_launch(void* const* d_in, const int* in_sizes, int n_in,
                              void* d_out, int out_size)
{
    // metadata order: x, encoder_x, Wq, bq, Wk, bk, Wv, bv, Wo, bo
    const float* x  = (const float*)d_in[0];
    const float* Wv = (const float*)d_in[6];
    const float* bv = (const float*)d_in[7];
    const float* Wo = (const float*)d_in[8];
    const float* bo = (const float*)d_in[9];
    float* out = (float*)d_out;

    float *WcT = nullptr, *Wot = nullptr, *c = nullptr;
    cudaGetSymbolAddress((void**)&WcT, g_WcT);
    cudaGetSymbolAddress((void**)&Wot, g_Wot);
    cudaGetSymbolAddress((void**)&c,   g_c);

    constexpr uint32_t SMEM_BIG   = 2u * (128 + 128) * 2 * LDS_B;  // 81920
    constexpr uint32_t SMEM_SMALL = 2u * (128 + 64)  * 2 * LDS_B;  // 61440
    cudaFuncSetAttribute((const void*)mma_gemm<128, 128, 64, 32>,
                         cudaFuncAttributeMaxDynamicSharedMemorySize, (int)SMEM_BIG);
    cudaFuncSetAttribute((const void*)mma_gemm<128, 64, 32, 32>,
                         cudaFuncAttributeMaxDynamicSharedMemorySize, (int)SMEM_SMALL);

    // 0) Wot = Wo^T
    transpose_1024<<<dim3(32, 32), dim3(32, 8)>>>(Wo, Wot);
    // 1) c = 2048 * bv @ Wo + bo
    bias_fold_kernel<<<1024, 256>>>(bv, Wo, bo, c);
    // 2) WcT[o,i] = sum_m Wot[o,m] * Wv[i,m]  -- 128x64 tiles, 128 CTAs
    mma_gemm<128, 64, 32, 32><<<dim3(16, 8), 256, SMEM_SMALL>>>(
        Wot, Wv, WcT, 1024, 1024, 1024, 1.0f, nullptr);
    // 3) out = 2048 * x @ WcT^T + c  -- 128x128 tiles, 512 CTAs
    mma_gemm<128, 128, 64, 32><<<dim3(8, 64), 256, SMEM_BIG>>>(
        x, WcT, out, 8192, 1024, 1024, 2048.0f, c);

    (void)in_sizes; (void)n_in; (void)out_size;
}

// round 6
// speedup vs baseline: 2.8424x; 1.0541x over previous
#include <cuda_runtime.h>
#include <cuda_bf16.h>
#include <cstdint>

// ===========================================================================
// out = 2048 * x @ (Wv @ Wo) + (2048 * bv @ Wo + bo)
// (softmax rows sum to 1; einsum 'bvhd,bhqk->bvhd' has no shared contraction
//  index, so attention collapses to scalar 2048)
//
// Warp-level mma.sync.m16n8k16 bf16 (tcgen05 blocked: bench ptxas targets
// sm_103). fp32 split into bf16 hi/lo; 3-term MMA (AhBh+AhBl+AlBh), issued
// term-major. R6: 128x64 CTA tile, 2 CTAs/SM (4 warps/SMSP) for latency
// hiding — R5 ran 1 CTA/SM at issue=25%, tensor=52%.
// ===========================================================================

__device__ float g_WcT[1024 * 1024];   // (Wv @ Wo)^T, fp32  (rows=o, K=i)
__device__ float g_Wot[1024 * 1024];   // Wo^T, fp32
__device__ float g_c[1024];            // 2048 * bv @ Wo + bo

__device__ __forceinline__ uint32_t smem_u32(const void* p) {
    uint32_t a;
    asm("{ .reg .u64 t; cvta.to.shared.u64 t, %1; cvt.u32.u64 %0, t; }"
        : "=r"(a) : "l"(p));
    return a;
}

__device__ __forceinline__ void ldsm4(uint32_t* r, uint32_t addr) {
    asm volatile("ldmatrix.sync.aligned.m8n8.x4.shared.b16 {%0,%1,%2,%3}, [%4];"
                 : "=r"(r[0]), "=r"(r[1]), "=r"(r[2]), "=r"(r[3]) : "r"(addr));
}

__device__ __forceinline__ void mma16816(float* c, const uint32_t* a, const uint32_t* b) {
    asm volatile(
        "mma.sync.aligned.m16n8k16.row.col.f32.bf16.bf16.f32 "
        "{%0,%1,%2,%3}, {%4,%5,%6,%7}, {%8,%9}, {%0,%1,%2,%3};"
        : "+f"(c[0]), "+f"(c[1]), "+f"(c[2]), "+f"(c[3])
        : "r"(a[0]), "r"(a[1]), "r"(a[2]), "r"(a[3]), "r"(b[0]), "r"(b[1]));
}

// bf16 [rows][32] tiles, padded row stride 40 bf16 (80 B): ldmatrix 8-row
// reads cover all 32 banks exactly once.
constexpr int LDS_B = 80;

// split float4 -> bf16 hi/lo, 8 B stores into (r, c4*4) of hi/lo matrices
__device__ __forceinline__ void sts_split(uint32_t hBase, uint32_t lBase,
                                          int r, int c4, float4 v) {
    __nv_bfloat16 h0 = __float2bfloat16_rn(v.x);
    __nv_bfloat16 h1 = __float2bfloat16_rn(v.y);
    __nv_bfloat16 h2 = __float2bfloat16_rn(v.z);
    __nv_bfloat16 h3 = __float2bfloat16_rn(v.w);
    __nv_bfloat16 l0 = __float2bfloat16_rn(v.x - __bfloat162float(h0));
    __nv_bfloat16 l1 = __float2bfloat16_rn(v.y - __bfloat162float(h1));
    __nv_bfloat16 l2 = __float2bfloat16_rn(v.z - __bfloat162float(h2));
    __nv_bfloat16 l3 = __float2bfloat16_rn(v.w - __bfloat162float(h3));
    const uint32_t off = (uint32_t)(r * LDS_B + c4 * 8);
    __nv_bfloat162 hp0 = __halves2bfloat162(h0, h1);
    __nv_bfloat162 hp1 = __halves2bfloat162(h2, h3);
    __nv_bfloat162 lp0 = __halves2bfloat162(l0, l1);
    __nv_bfloat162 lp1 = __halves2bfloat162(l2, l3);
    asm volatile("st.shared.v2.b32 [%0], {%1, %2};"
                 :: "r"(hBase + off),
                    "r"(*reinterpret_cast<uint32_t*>(&hp0)),
                    "r"(*reinterpret_cast<uint32_t*>(&hp1)));
    asm volatile("st.shared.v2.b32 [%0], {%1, %2};"
                 :: "r"(lBase + off),
                    "r"(*reinterpret_cast<uint32_t*>(&lp0)),
                    "r"(*reinterpret_cast<uint32_t*>(&lp1)));
}

// ---------------------------------------------------------------------------
// C[M,N] = alpha * A[M,K] @ B[N,K]^T + bias[N]
// A: [M,K] row-major fp32, B: [N,K] row-major fp32. CTA tile BM x BN, BK=32.
// 256 threads (8 warps), warp tile WM x WN. MIN_CTAS forces occupancy.
// ---------------------------------------------------------------------------
template <int BM, int BN, int WM, int WN, int MIN_CTAS>
__global__ void __launch_bounds__(256, MIN_CTAS)
mma_gemm(const float* __restrict__ A, const float* __restrict__ B,
         float* __restrict__ C, int M, int N, int K,
         float alpha, const float* __restrict__ bias)
{
    constexpr int WARPS_N = BN / WN;
    constexpr int MT  = WM / 16;             // 16-row mma tiles per warp
    constexpr int NTT = WN / 8;              // 8-col mma tiles per warp
    constexpr int NP  = WN / 16;             // 16-col ldsm groups per warp
    constexpr int A_IT = BM * 8 / 256;       // float4 loads per thread (A)
    constexpr int B_IT = BN * 8 / 256;       // float4 loads per thread (B)
    constexpr uint32_t OFF_ALO = (uint32_t)BM * LDS_B;
    constexpr uint32_t OFF_BHI = 2u * BM * LDS_B;
    constexpr uint32_t OFF_BLO = OFF_BHI + (uint32_t)BN * LDS_B;
    constexpr uint32_t STAGE   = 2u * (BM + BN) * LDS_B;

    extern __shared__ __align__(128) char smem_raw[];
    const uint32_t sb = smem_u32(smem_raw);

    const int tid = threadIdx.x;
    const int wid = tid >> 5;
    const int lane = tid & 31;
    const int warp_m = wid / WARPS_N;
    const int warp_n = wid % WARPS_N;
    const int row0 = blockIdx.y * BM;
    const int col0 = blockIdx.x * BN;

    // ldmatrix lane->addr offsets (bytes, within a matrix)
    const uint32_t aOff = (uint32_t)((warp_m * WM + (lane & 7) + ((lane >> 3) & 1) * 8) * LDS_B
                                     + (lane >> 4) * 16);
    const uint32_t bOff = (uint32_t)((warp_n * WN + (lane & 7) + ((lane >> 4) & 1) * 8) * LDS_B
                                     + ((lane >> 3) & 1) * 16);

    float acc[MT][NTT][4];
    #pragma unroll
    for (int mt = 0; mt < MT; mt++)
        #pragma unroll
        for (int nt = 0; nt < NTT; nt++)
            #pragma unroll
            for (int e = 0; e < 4; e++) acc[mt][nt][e] = 0.0f;

    const int NT = K >> 5;
    const int ldr = tid >> 3;
    const int ldc = tid & 7;

    float4 pa[A_IT], pb[B_IT];

    auto ldg = [&](int kt) {
        const int k0 = kt << 5;
        #pragma unroll
        for (int i = 0; i < A_IT; i++)
            pa[i] = *reinterpret_cast<const float4*>(
                A + (size_t)(row0 + ldr + i * 32) * K + k0 + ldc * 4);
        #pragma unroll
        for (int i = 0; i < B_IT; i++)
            pb[i] = *reinterpret_cast<const float4*>(
                B + (size_t)(col0 + ldr + i * 32) * K + k0 + ldc * 4);
    };
    auto sts = [&](int s) {
        const uint32_t base = sb + (uint32_t)s * STAGE;
        #pragma unroll
        for (int i = 0; i < A_IT; i++)
            sts_split(base, base + OFF_ALO, ldr + i * 32, ldc, pa[i]);
        #pragma unroll
        for (int i = 0; i < B_IT; i++)
            sts_split(base + OFF_BHI, base + OFF_BLO, ldr + i * 32, ldc, pb[i]);
    };
    auto compute = [&](int s) {
        const uint32_t base = sb + (uint32_t)s * STAGE;
        #pragma unroll
        for (int ks = 0; ks < 2; ks++) {
            uint32_t ah[MT][4], al[MT][4], bh[NP][4], bl[NP][4];
            #pragma unroll
            for (int mt = 0; mt < MT; mt++) {
                const uint32_t ad = base + aOff + (uint32_t)(mt * 16 * LDS_B + ks * 32);
                ldsm4(ah[mt], ad);
                ldsm4(al[mt], ad + OFF_ALO);
            }
            #pragma unroll
            for (int np = 0; np < NP; np++) {
                const uint32_t bd = base + OFF_BHI + bOff + (uint32_t)(np * 16 * LDS_B + ks * 32);
                ldsm4(bh[np], bd);
                ldsm4(bl[np], bd + (uint32_t)BN * LDS_B);
            }
            // term-major: dependent MMAs on one acc are MT*NTT apart
            #pragma unroll
            for (int mt = 0; mt < MT; mt++)
                #pragma unroll
                for (int nt = 0; nt < NTT; nt++)
                    mma16816(acc[mt][nt], ah[mt], &bh[nt >> 1][(nt & 1) * 2]);
            #pragma unroll
            for (int mt = 0; mt < MT; mt++)
                #pragma unroll
                for (int nt = 0; nt < NTT; nt++)
                    mma16816(acc[mt][nt], ah[mt], &bl[nt >> 1][(nt & 1) * 2]);
            #pragma unroll
            for (int mt = 0; mt < MT; mt++)
                #pragma unroll
                for (int nt = 0; nt < NTT; nt++)
                    mma16816(acc[mt][nt], al[mt], &bh[nt >> 1][(nt & 1) * 2]);
        }
    };

    ldg(0);
    sts(0);
    __syncthreads();

    for (int kt = 0; kt < NT; kt++) {
        const int s = kt & 1;
        if (kt + 1 < NT) ldg(kt + 1);
        compute(s);
        if (kt + 1 < NT) {
            sts(s ^ 1);
            __syncthreads();
        }
    }

    // ---- epilogue ----
    const int erow = row0 + warp_m * WM + (lane >> 2);
    const int ecol = col0 + warp_n * WN + (lane & 3) * 2;
    #pragma unroll
    for (int mt = 0; mt < MT; mt++) {
        #pragma unroll
        for (int nt = 0; nt < NTT; nt++) {
            const int cg = ecol + nt * 8;
            const float b0 = bias ? bias[cg]     : 0.0f;
            const float b1 = bias ? bias[cg + 1] : 0.0f;
            float2 v0, v1;
            v0.x = fmaf(alpha, acc[mt][nt][0], b0);
            v0.y = fmaf(alpha, acc[mt][nt][1], b1);
            v1.x = fmaf(alpha, acc[mt][nt][2], b0);
            v1.y = fmaf(alpha, acc[mt][nt][3], b1);
            *reinterpret_cast<float2*>(C + (size_t)(erow + mt * 16) * N + cg)     = v0;
            *reinterpret_cast<float2*>(C + (size_t)(erow + mt * 16 + 8) * N + cg) = v1;
        }
    }
}

// ---------------------------------------------------------------------------
__global__ void transpose_1024(const float* __restrict__ in, float* __restrict__ out) {
    __shared__ float t[32][33];
    const int bx = blockIdx.x * 32, by = blockIdx.y * 32;
    const int tx = threadIdx.x, ty = threadIdx.y;   // block 32x8
    #pragma unroll
    for (int i = 0; i < 32; i += 8)
        t[ty + i][tx] = in[(size_t)(by + ty + i) * 1024 + bx + tx];
    __syncthreads();
    #pragma unroll
    for (int i = 0; i < 32; i += 8)
        out[(size_t)(bx + ty + i) * 1024 + by + tx] = t[tx][ty + i];
}

__global__ void bias_fold_kernel(const float* __restrict__ bv,
                                 const float* __restrict__ Wo,
                                 const float* __restrict__ bo,
                                 float* __restrict__ c)
{
    __shared__ float red[256];
    const int j = blockIdx.x;
    float s = 0.0f;
    #pragma unroll 4
    for (int k = threadIdx.x; k < 1024; k += 256)
        s += bv[k] * Wo[k * 1024 + j];
    red[threadIdx.x] = s;
    __syncthreads();
    #pragma unroll
    for (int off = 128; off > 0; off >>= 1) {
        if (threadIdx.x < off) red[threadIdx.x] += red[threadIdx.x + off];
        __syncthreads();
    }
    if (threadIdx.x == 0) c[j] = 2048.0f * red[0] + bo[j];
}

// ---------------------------------------------------------------------------
extern "C" void kernel_launch(void* const* d_in, const int* in_sizes, int n_in,
                              void* d_out, int out_size)
{
    // metadata order: x, encoder_x, Wq, bq, Wk, bk, Wv, bv, Wo, bo
    const float* x  = (const float*)d_in[0];
    const float* Wv = (const float*)d_in[6];
    const float* bv = (const float*)d_in[7];
    const float* Wo = (const float*)d_in[8];
    const float* bo = (const float*)d_in[9];
    float* out = (float*)d_out;

    float *WcT = nullptr, *Wot = nullptr, *c = nullptr;
    cudaGetSymbolAddress((void**)&WcT, g_WcT);
    cudaGetSymbolAddress((void**)&Wot, g_Wot);
    cudaGetSymbolAddress((void**)&c,   g_c);

    constexpr uint32_t SMEM = 2u * (128 + 64) * 2 * LDS_B;   // 61440 per CTA
    cudaFuncSetAttribute((const void*)mma_gemm<128, 64, 32, 32, 2>,
                         cudaFuncAttributeMaxDynamicSharedMemorySize, (int)SMEM);

    // 0) Wot = Wo^T
    transpose_1024<<<dim3(32, 32), dim3(32, 8)>>>(Wo, Wot);
    // 1) c = 2048 * bv @ Wo + bo
    bias_fold_kernel<<<1024, 256>>>(bv, Wo, bo, c);
    // 2) WcT[o,i] = sum_m Wot[o,m] * Wv[i,m]  -- 128 CTAs, 2/SM
    mma_gemm<128, 64, 32, 32, 2><<<dim3(16, 8), 256, SMEM>>>(
        Wot, Wv, WcT, 1024, 1024, 1024, 1.0f, nullptr);
    // 3) out = 2048 * x @ WcT^T + c  -- 1024 CTAs, 2/SM
    mma_gemm<128, 64, 32, 32, 2><<<dim3(16, 64), 256, SMEM>>>(
        x, WcT, out, 8192, 1024, 1024, 2048.0f, c);

    (void)in_sizes; (void)n_in; (void)out_size;
}